// round 16
// baseline (speedup 1.0000x reference)
#include <cuda_runtime.h>

#define BB 64
#define TT 8000
#define SS 10
#define CHUNKS 11
#define ROWSPC ((TT + CHUNKS - 1) / CHUNKS)   // 728
#define NACC 110                              // 100 sel + 10 tot
#define FULL 0xFFFFFFFFu
#define FLT_MAX_C 3.402823466e+38f
#define LN2F 0.69314718055994530942f

// Scratch (no allocations allowed). Zero-initialized device globals.
__device__ float    g_part[BB * CHUNKS * NACC];
__device__ double   g_bsum[BB];
__device__ unsigned g_ticket2;

typedef unsigned long long u64;

__device__ __forceinline__ unsigned enc_f32(float x) {
    unsigned b = __float_as_uint(x);
    return (b & 0x80000000u) ? ~b : (b | 0x80000000u);
}
__device__ __forceinline__ float dec_f32(unsigned e) {
    unsigned b = (e & 0x80000000u) ? (e & 0x7FFFFFFFu) : ~e;
    return __uint_as_float(b);
}

// 10-way register select, 4-deep tree (idx in 0..9).
__device__ __forceinline__ float sel10(const float w[SS], int idx) {
    const float x01 = (idx & 1) ? w[1] : w[0];
    const float x23 = (idx & 1) ? w[3] : w[2];
    const float x45 = (idx & 1) ? w[5] : w[4];
    const float x67 = (idx & 1) ? w[7] : w[6];
    const float x89 = (idx & 1) ? w[9] : w[8];
    const float y03 = (idx & 2) ? x23 : x01;
    const float y47 = (idx & 2) ? x67 : x45;
    const float z07 = (idx & 4) ? y47 : y03;
    return (idx & 8) ? x89 : z07;
}

__device__ __forceinline__ int nib_get(u64 x, int i) {
    return (int)((x >> (i * 4)) & 15ull);
}
__device__ __forceinline__ u64 nib_set(u64 x, int i, int val) {
    const int s = i * 4;
    return (x & ~(15ull << s)) | ((u64)val << s);
}

// i-group table: sizes {3,2,3,2}, offsets {0,3,5,8}
template <int IG> struct IGrp;
template <> struct IGrp<0> { static const int OFF = 0, SZ = 3; };
template <> struct IGrp<1> { static const int OFF = 3, SZ = 2; };
template <> struct IGrp<2> { static const int OFF = 5, SZ = 3; };
template <> struct IGrp<3> { static const int OFF = 8, SZ = 2; };

// ---------------------------------------------------------------------------
// Kernel 1: pairwise BCE partial reduction — 8 classes (4 i-groups x 2
// j-halves), ONE warp per class per block. 704 blocks x 256 threads,
// 5 blocks/SM (62.5% occ). Accumulators <= 15 sel + 3 tot per thread.
// ---------------------------------------------------------------------------
template <int IG, int JH>
__device__ __forceinline__ void pw_body(const float* __restrict__ pred,
                                        const float* __restrict__ tgt,
                                        int b, int t0, int tend, int lane,
                                        float sel[IGrp<IG>::SZ][5],
                                        float tot[IGrp<IG>::SZ]) {
    const int ISZ = IGrp<IG>::SZ;
    for (int t = t0 + lane; t < tend; t += 32) {
        const size_t base = ((size_t)b * TT + (size_t)t) * SS;

        // tgt window [JH*4, JH*4+6): three aligned float2 (base is 8B-aligned).
        const float2* tp = reinterpret_cast<const float2*>(tgt + base + JH * 4);
        const float2 q0 = tp[0], q1 = tp[1], q2 = tp[2];
        const float te[6] = {q0.x, q0.y, q1.x, q1.y, q2.x, q2.y};

        // pred i-group loads (aligned pairs where possible).
        float pv[3];
        if (IG == 0) {
            const float2 a = *reinterpret_cast<const float2*>(pred + base);
            pv[0] = a.x; pv[1] = a.y; pv[2] = pred[base + 2];
        } else if (IG == 1) {
            pv[0] = pred[base + 3]; pv[1] = pred[base + 4]; pv[2] = 0.0f;
        } else if (IG == 2) {
            pv[0] = pred[base + 5];
            const float2 a = *reinterpret_cast<const float2*>(pred + base + 6);
            pv[1] = a.x; pv[2] = a.y;
        } else {
            const float2 a = *reinterpret_cast<const float2*>(pred + base + 8);
            pv[0] = a.x; pv[1] = a.y; pv[2] = 0.0f;
        }

        float diff[3];
#pragma unroll
        for (int ii = 0; ii < ISZ; ii++) {
            const float p  = pv[ii];
            const float l1 = __log2f(p);           // lg2(p)
            const float l2 = __log2f(1.0f - p);    // lg2(1-p); p in [0.01, 0.99]
            diff[ii] = l1 - l2;
            tot[ii] += l2;
        }
#pragma unroll
        for (int jj = 0; jj < 5; jj++) {
            const float tj = te[jj + JH];          // exactly 0.0f or 1.0f
#pragma unroll
            for (int ii = 0; ii < ISZ; ii++)
                sel[ii][jj] = fmaf(diff[ii], tj, sel[ii][jj]);
        }
    }
}

template <int IG, int JH>
__device__ __forceinline__ void pw_run(const float* __restrict__ pred,
                                       const float* __restrict__ tgt,
                                       int b, int t0, int tend, int lane,
                                       float sstash[18]) {
    const int ISZ = IGrp<IG>::SZ;
    float sel[IGrp<IG>::SZ][5];
    float tot[IGrp<IG>::SZ];
#pragma unroll
    for (int ii = 0; ii < ISZ; ii++) {
        tot[ii] = 0.0f;
#pragma unroll
        for (int jj = 0; jj < 5; jj++) sel[ii][jj] = 0.0f;
    }

    pw_body<IG, JH>(pred, tgt, b, t0, tend, lane, sel, tot);

    // Full-warp tree reduction -> lane 0.
#pragma unroll
    for (int ii = 0; ii < ISZ; ii++) {
#pragma unroll
        for (int jj = 0; jj < 5; jj++) {
            float v = sel[ii][jj];
#pragma unroll
            for (int o = 16; o; o >>= 1) v += __shfl_down_sync(FULL, v, o);
            sel[ii][jj] = v;
        }
        float v = tot[ii];
#pragma unroll
        for (int o = 16; o; o >>= 1) v += __shfl_down_sync(FULL, v, o);
        tot[ii] = v;
    }
    if (lane == 0) {
#pragma unroll
        for (int ii = 0; ii < ISZ; ii++) {
#pragma unroll
            for (int jj = 0; jj < 5; jj++) sstash[ii * 5 + jj] = sel[ii][jj];
            if (JH == 0) sstash[15 + ii] = tot[ii];
        }
    }
}

__global__ __launch_bounds__(256, 5) void pairwise_kernel(const float* __restrict__ pred,
                                                          const float* __restrict__ tgt) {
    __shared__ float s[8][18];
    const int b    = blockIdx.x / CHUNKS;
    const int c    = blockIdx.x % CHUNKS;
    const int tid  = threadIdx.x;
    const int lane = tid & 31;
    const int w    = tid >> 5;                // class: ig = w>>1, jh = w&1

    const int t0   = c * ROWSPC;
    const int tend = (t0 + ROWSPC < TT) ? (t0 + ROWSPC) : TT;

    switch (w) {
        case 0: pw_run<0, 0>(pred, tgt, b, t0, tend, lane, s[0]); break;
        case 1: pw_run<0, 1>(pred, tgt, b, t0, tend, lane, s[1]); break;
        case 2: pw_run<1, 0>(pred, tgt, b, t0, tend, lane, s[2]); break;
        case 3: pw_run<1, 1>(pred, tgt, b, t0, tend, lane, s[3]); break;
        case 4: pw_run<2, 0>(pred, tgt, b, t0, tend, lane, s[4]); break;
        case 5: pw_run<2, 1>(pred, tgt, b, t0, tend, lane, s[5]); break;
        case 6: pw_run<3, 0>(pred, tgt, b, t0, tend, lane, s[6]); break;
        default: pw_run<3, 1>(pred, tgt, b, t0, tend, lane, s[7]); break;
    }
    __syncthreads();

    if (tid < NACC) {
        float val;
        if (tid < 100) {
            const int i = tid / 10, j = tid % 10;
            const int ig = (i < 3) ? 0 : (i < 5) ? 1 : (i < 8) ? 2 : 3;
            const int ioff = (ig == 0) ? 0 : (ig == 1) ? 3 : (ig == 2) ? 5 : 8;
            const int jh = (j >= 5);
            val = s[ig * 2 + jh][(i - ioff) * 5 + (j % 5)];
        } else {
            const int i = tid - 100;
            const int ig = (i < 3) ? 0 : (i < 5) ? 1 : (i < 8) ? 2 : 3;
            const int ioff = (ig == 0) ? 0 : (ig == 1) ? 3 : (ig == 2) ? 5 : 8;
            val = s[ig * 2][15 + (i - ioff)];
        }
        g_part[(b * CHUNKS + c) * NACC + tid] = val * LN2F;   // lg2 -> ln once
    }
}

// ---------------------------------------------------------------------------
// Kernel 2: warp-per-batch Hungarian (r10 FROZEN: JV, warm start + greedy,
// one REDUX per Dijkstra iteration, uniform nibble-packed p64) + fused mean.
// ---------------------------------------------------------------------------
__global__ __launch_bounds__(128) void hungarian_kernel(float* __restrict__ out) {
    __shared__ float s_cost[100];
    const int b   = blockIdx.x;
    const int tid = threadIdx.x;
    const int lane = tid & 31;

    if (tid < 100) {
        const int i = tid / 10;
        float sl = 0.0f, to = 0.0f;
#pragma unroll
        for (int c = 0; c < CHUNKS; c++) {
            const float* gp = &g_part[(b * CHUNKS + c) * NACC];
            sl += __ldcg(&gp[tid]);
            to += __ldcg(&gp[100 + i]);
        }
        s_cost[tid] = -(to + sl) * (1.0f / (float)TT);
    }
    __syncthreads();
    if (tid >= 32) return;

    const bool isCol = (lane >= 1 && lane <= SS);
    const int  cl    = isCol ? (lane - 1) : 0;

    float colv[SS];
#pragma unroll
    for (int i = 0; i < SS; i++) colv[i] = s_cost[i * 10 + cl];

    // Warm start: v[j] = min_i colv (lane); u[i] = min_j (colv[i]-v) (uniform).
    float v = 0.0f;
    if (isCol) {
        float mn = colv[0];
#pragma unroll
        for (int i = 1; i < SS; i++) mn = fminf(mn, colv[i]);
        v = mn;
    }
    float uu[SS];
#pragma unroll
    for (int i = 0; i < SS; i++) {
        const float t = isCol ? (colv[i] - v) : FLT_MAX_C;
        uu[i] = dec_f32(__reduce_min_sync(FULL, enc_f32(t)));   // exact (full key)
    }

    // Greedy tight-edge pre-assignment (p64 kept uniform in all lanes).
    u64 p64 = 0ull;
    int way = 0;                       // lane j: alternating-path parent
    unsigned rowdone = 0u;
#pragma unroll
    for (int i = 1; i <= SS; i++) {
        const float red = isCol ? ((colv[i - 1] - v) - uu[i - 1]) : 1.0f;
        const bool  z   = isCol && (nib_get(p64, lane) == 0) && (red == 0.0f);
        const unsigned bal = __ballot_sync(FULL, z);
        if (bal) {
            const int j = __ffs(bal) - 1;
            p64 = nib_set(p64, j, i);                   // uniform update
            rowdone |= 1u << i;
        }
    }

    // Dijkstra per remaining free row: ONE collective (REDUX.MIN) per iter.
    for (int root = 1; root <= SS; root++) {
        if ((rowdone >> root) & 1u) continue;
        p64 = nib_set(p64, 0, root);                    // p[0] = root

        float wv[SS];
#pragma unroll
        for (int i = 0; i < SS; i++)
            wv[i] = isCol ? ((colv[i] - uu[i]) - v) : FLT_MAX_C;

        float minv = FLT_MAX_C;
        unsigned used = 1u;            // virtual column 0
        unsigned rowm = 0u;
        int j0 = 0, i0 = root;

        while (true) {
            rowm |= 1u << i0;

            const bool  active = isCol && !((used >> lane) & 1u);
            const float cur    = sel10(wv, i0 - 1);
            if (active && cur < minv) { minv = cur; way = j0; }

            const unsigned key = active ? ((enc_f32(minv) & 0xFFFFFFE0u) | (unsigned)lane)
                                        : 0xFFFFFFFFu;
            const unsigned m   = __reduce_min_sync(FULL, key);
            const int      j1  = (int)(m & 31u);
            const float delta  = dec_f32(m & 0xFFFFFFE0u);  // <=exact by <32ulp; feasible
            const int   pn     = nib_get(p64, j1);          // uniform ALU, no shfl

            if (lane <= SS) {
                if ((used >> lane) & 1u) v -= delta;
                else                     minv -= delta;
            }
#pragma unroll
            for (int i = 1; i <= SS; i++)
                if ((rowm >> i) & 1u) uu[i - 1] += delta;   // uniform

            used |= 1u << j1;
            j0 = j1;
            if (pn == 0) break;
            i0 = pn;
        }

        // Augment along the alternating path (p64 stays uniform).
        while (j0) {
            const int jprev = __shfl_sync(FULL, way, j0);
            p64 = nib_set(p64, j0, nib_get(p64, jprev));
            j0 = jprev;
        }
    }

    // Matched sum (exact f32 cost entries, f64 accumulate).
    double val = 0.0;
    if (isCol) val = (double)s_cost[(nib_get(p64, lane) - 1) * 10 + cl];
#pragma unroll
    for (int o = 16; o; o >>= 1) val += __shfl_down_sync(FULL, val, o);
    if (lane == 0) g_bsum[b] = val;

    // Fused finalize: last block computes the mean.
    __threadfence();
    unsigned t2 = 0;
    if (lane == 0) t2 = atomicAdd(&g_ticket2, 1u);
    t2 = __shfl_sync(FULL, t2, 0);
    if (t2 == BB - 1) {
        if (lane == 0) g_ticket2 = 0;              // reset for graph replay
        __threadfence();
        double x = __ldcg(&g_bsum[lane]) + __ldcg(&g_bsum[lane + 32]);
#pragma unroll
        for (int o = 16; o; o >>= 1) x += __shfl_down_sync(FULL, x, o);
        if (lane == 0) out[0] = (float)(x / (double)(BB * SS));
    }
}

extern "C" void kernel_launch(void* const* d_in, const int* in_sizes, int n_in,
                              void* d_out, int out_size) {
    const float* pred = (const float*)d_in[0];
    const float* tgt  = (const float*)d_in[1];
    pairwise_kernel<<<BB * CHUNKS, 256>>>(pred, tgt);
    hungarian_kernel<<<BB, 128>>>((float*)d_out);
}

// round 17
// speedup vs baseline: 1.0918x; 1.0918x over previous
#include <cuda_runtime.h>

#define BB 64
#define TT 8000
#define SS 10
#define CHUNKS 8
#define ROWSPC (TT / CHUNKS)                  // 1000 rows per block
#define NTILE 4
#define TROWS 250                             // rows per tile (exact)
#define TFLOATS (TROWS * SS)                  // 2500 floats per array per tile
#define TF4 (TFLOATS / 4)                     // 625 float4
#define NACC 110                              // 100 sel + 10 tot
#define FULL 0xFFFFFFFFu
#define FLT_MAX_C 3.402823466e+38f
#define LN2F 0.69314718055994530942f

// Scratch (no allocations allowed). Zero-initialized device globals.
__device__ float    g_part[BB * CHUNKS * NACC];
__device__ double   g_bsum[BB];
__device__ unsigned g_ticket2;

typedef unsigned long long u64;

__device__ __forceinline__ unsigned enc_f32(float x) {
    unsigned b = __float_as_uint(x);
    return (b & 0x80000000u) ? ~b : (b | 0x80000000u);
}
__device__ __forceinline__ float dec_f32(unsigned e) {
    unsigned b = (e & 0x80000000u) ? (e & 0x7FFFFFFFu) : ~e;
    return __uint_as_float(b);
}

// 10-way register select, 4-deep tree (idx in 0..9).
__device__ __forceinline__ float sel10(const float w[SS], int idx) {
    const float x01 = (idx & 1) ? w[1] : w[0];
    const float x23 = (idx & 1) ? w[3] : w[2];
    const float x45 = (idx & 1) ? w[5] : w[4];
    const float x67 = (idx & 1) ? w[7] : w[6];
    const float x89 = (idx & 1) ? w[9] : w[8];
    const float y03 = (idx & 2) ? x23 : x01;
    const float y47 = (idx & 2) ? x67 : x45;
    const float z07 = (idx & 4) ? y47 : y03;
    return (idx & 8) ? x89 : z07;
}

__device__ __forceinline__ int nib_get(u64 x, int i) {
    return (int)((x >> (i * 4)) & 15ull);
}
__device__ __forceinline__ u64 nib_set(u64 x, int i, int val) {
    const int s = i * 4;
    return (x & ~(15ull << s)) | ((u64)val << s);
}

// ---------------------------------------------------------------------------
// Kernel 1: pairwise BCE — r6 class accumulation, but fed from smem.
// 512 blocks x 256 threads, 4 blocks/SM, one wave. Per 250-row tile:
//   stage : verbatim float4 copy GMEM -> smem (coalesced LDG.128 +
//           contiguous STS.128, zero scatter)
//   accum : FROZEN r6 body, LDS.64 (2-way bank conflict) instead of the
//           40B-strided LDG.64 (10 L1 wavefronts) that bound the kernel.
// ---------------------------------------------------------------------------
template <int IH, int JH>
__device__ __forceinline__ void pw_tile(const float* __restrict__ bp,
                                        const float* __restrict__ bt,
                                        int slot, float sel[5][5], float tot[5]) {
#pragma unroll
    for (int m = 0; m < 4; m++) {
        const int r = slot + 64 * m;
        if (m < 3 || r < TROWS) {
            const float2* dw = reinterpret_cast<const float2*>(bp + r * SS + IH * 4);
            const float2* tw = reinterpret_cast<const float2*>(bt + r * SS + JH * 4);
            const float2 d0 = dw[0], d1 = dw[1], d2 = dw[2];
            const float2 t0 = tw[0], t1 = tw[1], t2 = tw[2];
            const float pe[6] = {d0.x, d0.y, d1.x, d1.y, d2.x, d2.y};
            const float te[6] = {t0.x, t0.y, t1.x, t1.y, t2.x, t2.y};

            float diff[5];
#pragma unroll
            for (int ii = 0; ii < 5; ii++) {
                const float p  = pe[ii + IH];          // static index
                const float l1 = __log2f(p);           // lg2(p)
                const float l2 = __log2f(1.0f - p);    // lg2(1-p)
                diff[ii] = l1 - l2;
                tot[ii] += l2;
            }
#pragma unroll
            for (int jj = 0; jj < 5; jj++) {
                const float tj = te[jj + JH];          // exactly 0.0f or 1.0f
#pragma unroll
                for (int ii = 0; ii < 5; ii++)
                    sel[ii][jj] = fmaf(diff[ii], tj, sel[ii][jj]);
            }
        }
    }
}

__global__ __launch_bounds__(256, 4) void pairwise_kernel(const float* __restrict__ pred,
                                                          const float* __restrict__ tgt) {
    __shared__ float bp[TFLOATS];
    __shared__ float bt[TFLOATS];
    __shared__ float s[8][30];

    const int b    = blockIdx.x / CHUNKS;
    const int c    = blockIdx.x % CHUNKS;
    const int tid  = threadIdx.x;
    const int lane = tid & 31;
    const int w    = tid >> 5;
    const int q    = w >> 1;                  // warp class: IH = q&1, JH = q>>1
    const int slot = tid & 63;

    const float* pg = pred + (size_t)(b * TT + c * ROWSPC) * SS;
    const float* tg = tgt  + (size_t)(b * TT + c * ROWSPC) * SS;

    float sel[5][5];
    float tot[5];
#pragma unroll
    for (int ii = 0; ii < 5; ii++) {
        tot[ii] = 0.0f;
#pragma unroll
        for (int jj = 0; jj < 5; jj++) sel[ii][jj] = 0.0f;
    }

    for (int k = 0; k < NTILE; k++) {
        // ---- stage: verbatim coalesced copy ----
        {
            const float4* pg4 = reinterpret_cast<const float4*>(pg + k * TFLOATS);
            const float4* tg4 = reinterpret_cast<const float4*>(tg + k * TFLOATS);
            float4* bp4 = reinterpret_cast<float4*>(bp);
            float4* bt4 = reinterpret_cast<float4*>(bt);
            for (int u = tid; u < TF4; u += 256) {
                bp4[u] = pg4[u];
                bt4[u] = tg4[u];
            }
        }
        __syncthreads();

        // ---- accumulate (frozen r6 body, smem-fed) ----
        switch (q) {
            case 0: pw_tile<0, 0>(bp, bt, slot, sel, tot); break;
            case 1: pw_tile<1, 0>(bp, bt, slot, sel, tot); break;
            case 2: pw_tile<0, 1>(bp, bt, slot, sel, tot); break;
            default: pw_tile<1, 1>(bp, bt, slot, sel, tot); break;
        }
        __syncthreads();
    }

    // Full-warp tree reduction of the 30 accumulators -> lane 0.
#pragma unroll
    for (int ii = 0; ii < 5; ii++) {
#pragma unroll
        for (int jj = 0; jj < 5; jj++) {
            float v = sel[ii][jj];
#pragma unroll
            for (int o = 16; o; o >>= 1) v += __shfl_down_sync(FULL, v, o);
            sel[ii][jj] = v;
        }
        float v = tot[ii];
#pragma unroll
        for (int o = 16; o; o >>= 1) v += __shfl_down_sync(FULL, v, o);
        tot[ii] = v;
    }

    if (lane == 0) {
#pragma unroll
        for (int ii = 0; ii < 5; ii++) {
#pragma unroll
            for (int jj = 0; jj < 5; jj++) s[w][ii * 5 + jj] = sel[ii][jj];
            s[w][25 + ii] = tot[ii];
        }
    }
    __syncthreads();

    if (tid < NACC) {
        int qq, idx;
        if (tid < 100) {
            const int i = tid / 10, j = tid % 10;
            const int ih = (i >= 5), jh = (j >= 5);
            qq  = jh * 2 + ih;
            idx = (i % 5) * 5 + (j % 5);
        } else {
            const int i = tid - 100;
            const int ih = (i >= 5);
            qq  = ih;                      // tot kept only by jhalf==0 classes
            idx = 25 + (i % 5);
        }
        g_part[(b * CHUNKS + c) * NACC + tid] =
            (s[2 * qq][idx] + s[2 * qq + 1][idx]) * LN2F;   // lg2 -> ln once
    }
}

// ---------------------------------------------------------------------------
// Kernel 2: warp-per-batch Hungarian (r10 FROZEN: JV, warm start + greedy,
// one REDUX per Dijkstra iteration, uniform nibble-packed p64) + fused mean.
// ---------------------------------------------------------------------------
__global__ __launch_bounds__(128) void hungarian_kernel(float* __restrict__ out) {
    __shared__ float s_cost[100];
    const int b   = blockIdx.x;
    const int tid = threadIdx.x;
    const int lane = tid & 31;

    if (tid < 100) {
        const int i = tid / 10;
        float sl = 0.0f, to = 0.0f;
#pragma unroll
        for (int c = 0; c < CHUNKS; c++) {
            const float* gp = &g_part[(b * CHUNKS + c) * NACC];
            sl += __ldcg(&gp[tid]);
            to += __ldcg(&gp[100 + i]);
        }
        s_cost[tid] = -(to + sl) * (1.0f / (float)TT);
    }
    __syncthreads();
    if (tid >= 32) return;

    const bool isCol = (lane >= 1 && lane <= SS);
    const int  cl    = isCol ? (lane - 1) : 0;

    float colv[SS];
#pragma unroll
    for (int i = 0; i < SS; i++) colv[i] = s_cost[i * 10 + cl];

    // Warm start: v[j] = min_i colv (lane); u[i] = min_j (colv[i]-v) (uniform).
    float v = 0.0f;
    if (isCol) {
        float mn = colv[0];
#pragma unroll
        for (int i = 1; i < SS; i++) mn = fminf(mn, colv[i]);
        v = mn;
    }
    float uu[SS];
#pragma unroll
    for (int i = 0; i < SS; i++) {
        const float t = isCol ? (colv[i] - v) : FLT_MAX_C;
        uu[i] = dec_f32(__reduce_min_sync(FULL, enc_f32(t)));   // exact (full key)
    }

    // Greedy tight-edge pre-assignment (p64 kept uniform in all lanes).
    u64 p64 = 0ull;
    int way = 0;                       // lane j: alternating-path parent
    unsigned rowdone = 0u;
#pragma unroll
    for (int i = 1; i <= SS; i++) {
        const float red = isCol ? ((colv[i - 1] - v) - uu[i - 1]) : 1.0f;
        const bool  z   = isCol && (nib_get(p64, lane) == 0) && (red == 0.0f);
        const unsigned bal = __ballot_sync(FULL, z);
        if (bal) {
            const int j = __ffs(bal) - 1;
            p64 = nib_set(p64, j, i);                   // uniform update
            rowdone |= 1u << i;
        }
    }

    // Dijkstra per remaining free row: ONE collective (REDUX.MIN) per iter.
    for (int root = 1; root <= SS; root++) {
        if ((rowdone >> root) & 1u) continue;
        p64 = nib_set(p64, 0, root);                    // p[0] = root

        float wv[SS];
#pragma unroll
        for (int i = 0; i < SS; i++)
            wv[i] = isCol ? ((colv[i] - uu[i]) - v) : FLT_MAX_C;

        float minv = FLT_MAX_C;
        unsigned used = 1u;            // virtual column 0
        unsigned rowm = 0u;
        int j0 = 0, i0 = root;

        while (true) {
            rowm |= 1u << i0;

            const bool  active = isCol && !((used >> lane) & 1u);
            const float cur    = sel10(wv, i0 - 1);
            if (active && cur < minv) { minv = cur; way = j0; }

            const unsigned key = active ? ((enc_f32(minv) & 0xFFFFFFE0u) | (unsigned)lane)
                                        : 0xFFFFFFFFu;
            const unsigned m   = __reduce_min_sync(FULL, key);
            const int      j1  = (int)(m & 31u);
            const float delta  = dec_f32(m & 0xFFFFFFE0u);  // <=exact by <32ulp; feasible
            const int   pn     = nib_get(p64, j1);          // uniform ALU, no shfl

            if (lane <= SS) {
                if ((used >> lane) & 1u) v -= delta;
                else                     minv -= delta;
            }
#pragma unroll
            for (int i = 1; i <= SS; i++)
                if ((rowm >> i) & 1u) uu[i - 1] += delta;   // uniform

            used |= 1u << j1;
            j0 = j1;
            if (pn == 0) break;
            i0 = pn;
        }

        // Augment along the alternating path (p64 stays uniform).
        while (j0) {
            const int jprev = __shfl_sync(FULL, way, j0);
            p64 = nib_set(p64, j0, nib_get(p64, jprev));
            j0 = jprev;
        }
    }

    // Matched sum (exact f32 cost entries, f64 accumulate).
    double val = 0.0;
    if (isCol) val = (double)s_cost[(nib_get(p64, lane) - 1) * 10 + cl];
#pragma unroll
    for (int o = 16; o; o >>= 1) val += __shfl_down_sync(FULL, val, o);
    if (lane == 0) g_bsum[b] = val;

    // Fused finalize: last block computes the mean.
    __threadfence();
    unsigned t2 = 0;
    if (lane == 0) t2 = atomicAdd(&g_ticket2, 1u);
    t2 = __shfl_sync(FULL, t2, 0);
    if (t2 == BB - 1) {
        if (lane == 0) g_ticket2 = 0;              // reset for graph replay
        __threadfence();
        double x = __ldcg(&g_bsum[lane]) + __ldcg(&g_bsum[lane + 32]);
#pragma unroll
        for (int o = 16; o; o >>= 1) x += __shfl_down_sync(FULL, x, o);
        if (lane == 0) out[0] = (float)(x / (double)(BB * SS));
    }
}

extern "C" void kernel_launch(void* const* d_in, const int* in_sizes, int n_in,
                              void* d_out, int out_size) {
    const float* pred = (const float*)d_in[0];
    const float* tgt  = (const float*)d_in[1];
    pairwise_kernel<<<BB * CHUNKS, 256>>>(pred, tgt);
    hungarian_kernel<<<BB, 128>>>((float*)d_out);
}